// round 12
// baseline (speedup 1.0000x reference)
#include <cuda_runtime.h>
#include <cuda_fp16.h>
#include <math.h>
#include <stdint.h>

// Problem dims (fixed)
#define Bq 2
#define Tt 2048
#define Mm 1024
#define Hh 8
#define Dd 128
#define BT (Bq*Tt)      // 4096
#define HD (Hh*Dd)      // 1024

// Scratch — no cudaMalloc allowed
__device__ __half g_xh[BT*Mm];         // fp16 x
__device__ __half g_wqt[Mm*HD];        // fp16 wq^T [N][K]
__device__ __half g_wkt[Mm*HD];
__device__ __half g_wvt[Mm*HD];
__device__ __half g_wot[HD*Mm];        // fp16 wo^T [N=Mm][K=HD]
__device__ __half g_qh[BT*HD];         // fp16 q (normed/roped) [b,h,t,d]
__device__ __half g_kh[BT*HD];         // fp16 k [b,h,t,d]
__device__ __half g_vt[BT*HD];         // fp16 v transposed [b,h,d,t]
__device__ __half g_oh[BT*HD];         // fp16 attention out [b,t,h,d]
__device__ float4 g_rope[Tt*32];       // (cos0,sin0,cos1,sin1) per (t, d-pair)

__device__ __forceinline__ void mma_f16(float c[4], uint32_t a0, uint32_t a1,
                                        uint32_t a2, uint32_t a3,
                                        uint32_t b0, uint32_t b1) {
    asm volatile(
        "mma.sync.aligned.m16n8k16.row.col.f32.f16.f16.f32 "
        "{%0,%1,%2,%3}, {%4,%5,%6,%7}, {%8,%9}, {%0,%1,%2,%3};\n"
        : "+f"(c[0]), "+f"(c[1]), "+f"(c[2]), "+f"(c[3])
        : "r"(a0), "r"(a1), "r"(a2), "r"(a3), "r"(b0), "r"(b1));
}

__device__ __forceinline__ void ldsm4(uint32_t& r0, uint32_t& r1,
                                      uint32_t& r2, uint32_t& r3, uint32_t addr) {
    asm volatile("ldmatrix.sync.aligned.m8n8.x4.shared.b16 {%0,%1,%2,%3}, [%4];"
                 : "=r"(r0), "=r"(r1), "=r"(r2), "=r"(r3) : "r"(addr));
}

__device__ __forceinline__ uint32_t packh2(float lo, float hi) {
    __half2 h = __floats2half2_rn(lo, hi);
    return *(uint32_t*)&h;
}

__device__ __forceinline__ void cp16(uint32_t dst, const void* src) {
    asm volatile("cp.async.ca.shared.global [%0], [%1], 16;\n" :: "r"(dst), "l"(src));
}
#define CP_COMMIT() asm volatile("cp.async.commit_group;\n" ::: "memory")
#define CP_WAIT(n)  asm volatile("cp.async.wait_group %0;\n" :: "n"(n) : "memory")

// ---------------------------------------------------------------------------
__global__ __launch_bounds__(256) void f2h(const float* __restrict__ src,
                                           __half* __restrict__ dst, int n4) {
    int i = blockIdx.x * blockDim.x + threadIdx.x;
    if (i < n4) {
        float4 v = ((const float4*)src)[i];
        ((uint2*)dst)[i] = make_uint2(packh2(v.x, v.y), packh2(v.z, v.w));
    }
}

// ---------------------------------------------------------------------------
// RoPE table init: tab[t*32 + p] = (cos(t*f_{2p}), sin(t*f_{2p}),
//                                   cos(t*f_{2p+1}), sin(t*f_{2p+1}))
// ---------------------------------------------------------------------------
__global__ __launch_bounds__(256) void rope_init(float4* __restrict__ tab) {
    int idx = blockIdx.x * blockDim.x + threadIdx.x;   // 0 .. Tt*32-1
    if (idx >= Tt * 32) return;
    int t = idx >> 5, p = idx & 31;
    const float c64 = -0.20762050593017578f;           // -log2(10000)/64
    float f0 = exp2f((float)(2 * p) * c64);
    float f1 = exp2f((float)(2 * p + 1) * c64);
    float s0, c0, s1, c1;
    __sincosf((float)t * f0, &s0, &c0);
    __sincosf((float)t * f1, &s1, &c1);
    tab[idx] = make_float4(c0, s0, c1, s1);
}

// ---------------------------------------------------------------------------
// Weight transpose + fp16: w [1024][1024] fp32 -> wt fp16 (w^T). z: which.
// ---------------------------------------------------------------------------
__global__ __launch_bounds__(256) void wtrans(const float* __restrict__ w0,
                                              const float* __restrict__ w1,
                                              const float* __restrict__ w2,
                                              const float* __restrict__ w3,
                                              __half* __restrict__ o0,
                                              __half* __restrict__ o1,
                                              __half* __restrict__ o2,
                                              __half* __restrict__ o3) {
    const float* w = (blockIdx.z == 0) ? w0 : (blockIdx.z == 1) ? w1
                     : (blockIdx.z == 2) ? w2 : w3;
    __half* o = (blockIdx.z == 0) ? o0 : (blockIdx.z == 1) ? o1
                : (blockIdx.z == 2) ? o2 : o3;
    __shared__ __half tile[32][33];
    const int tx = threadIdx.x, ty = threadIdx.y;
    const int k0 = blockIdx.x * 32, n0 = blockIdx.y * 32;
#pragma unroll
    for (int i = 0; i < 4; i++)
        tile[ty + i * 8][tx] = __float2half_rn(w[(size_t)(k0 + ty + i * 8) * 1024 + n0 + tx]);
    __syncthreads();
#pragma unroll
    for (int i = 0; i < 4; i++)
        o[(size_t)(n0 + ty + i * 8) * 1024 + k0 + tx] = tile[tx][ty + i * 8];
}

// ---------------------------------------------------------------------------
// Fused QKV GEMM with per-head epilogue (table-based RoPE; coalesced V).
// z=0: q -> RMSNorm+RoPE -> g_qh [b,h,t,d]
// z=1: k -> RMSNorm+RoPE -> g_kh [b,h,t,d]
// z=2: v -> smem-staged transposed write -> g_vt [b,h,d,t]
// ---------------------------------------------------------------------------
#define HGSTR 20
#define GW (128*HGSTR)   // 2560 words per buffer

__global__ __launch_bounds__(256, 2) void gemm_qkv(const __half* __restrict__ A,
                                                   const __half* __restrict__ B0,
                                                   const __half* __restrict__ B1,
                                                   const __half* __restrict__ B2,
                                                   __half* __restrict__ qh,
                                                   __half* __restrict__ kh,
                                                   __half* __restrict__ vt,
                                                   const float4* __restrict__ rope) {
    const int z = blockIdx.z;
    const __half* Bt = (z == 0) ? B0 : (z == 1) ? B1 : B2;

    __shared__ uint32_t smx[4 * GW];            // As[2] | Bs[2]; aliased by tile
    uint32_t* sAb = smx;
    uint32_t* sBb = smx + 2 * GW;
    __half*   tile = (__half*)smx;              // epilogue: [128][136] halfs

    const int tid  = threadIdx.x;
    const int lane = tid & 31;
    const int warp = tid >> 5;
    const int gid  = lane >> 2;
    const int tig  = lane & 3;
    const int lm   = lane >> 3;
    const int lr   = lane & 7;
    const int wm   = (warp >> 1) * 32;
    const int wn   = (warp & 1) * 64;
    const int rowBase = blockIdx.y * 128;
    const int colBase = blockIdx.x * 128;
    const int K = Mm;

    const __half* Ag = A + (size_t)rowBase * K;
    const __half* Bg = Bt + (size_t)colBase * K;
    const uint32_t sA = (uint32_t)__cvta_generic_to_shared(sAb);
    const uint32_t sB = (uint32_t)__cvta_generic_to_shared(sBb);

    float acc[2][8][4];
#pragma unroll
    for (int mt = 0; mt < 2; mt++)
#pragma unroll
        for (int nt = 0; nt < 8; nt++)
#pragma unroll
            for (int i = 0; i < 4; i++) acc[mt][nt][i] = 0.f;

    {
#pragma unroll
        for (int i = 0; i < 2; i++) {
            const int s = tid + i * 256;
            const int r = s >> 2, c = s & 3;
            cp16(sA + (r * HGSTR + c * 4) * 4, Ag + (size_t)r * K + c * 8);
            cp16(sB + (r * HGSTR + c * 4) * 4, Bg + (size_t)r * K + c * 8);
        }
        CP_COMMIT();
    }

    const int niter = K >> 5;
    for (int it = 0; it < niter; it++) {
        const int cur = it & 1;
        if (it + 1 < niter) {
            const int k0 = (it + 1) << 5;
            const int nxt = (it + 1) & 1;
#pragma unroll
            for (int i = 0; i < 2; i++) {
                const int s = tid + i * 256;
                const int r = s >> 2, c = s & 3;
                cp16(sA + (nxt * GW + r * HGSTR + c * 4) * 4,
                     Ag + (size_t)r * K + k0 + c * 8);
                cp16(sB + (nxt * GW + r * HGSTR + c * 4) * 4,
                     Bg + (size_t)r * K + k0 + c * 8);
            }
            CP_COMMIT();
            CP_WAIT(1);
        } else {
            CP_WAIT(0);
        }
        __syncthreads();

        const uint32_t sAc = sA + cur * GW * 4;
        const uint32_t sBc = sB + cur * GW * 4;
#pragma unroll
        for (int kh2 = 0; kh2 < 2; kh2++) {
            const int kk = kh2 * 8;
            uint32_t af[2][4];
#pragma unroll
            for (int mt = 0; mt < 2; mt++) {
                const int row = wm + mt * 16 + (lm & 1) * 8 + lr;
                const int word = kk + (lm >> 1) * 4;
                ldsm4(af[mt][0], af[mt][1], af[mt][2], af[mt][3],
                      sAc + (row * HGSTR + word) * 4);
            }
#pragma unroll
            for (int np = 0; np < 4; np++) {
                const int row = wn + (2 * np + (lm >> 1)) * 8 + lr;
                const int word = kk + (lm & 1) * 4;
                uint32_t b00, b01, b10, b11;
                ldsm4(b00, b01, b10, b11, sBc + (row * HGSTR + word) * 4);
#pragma unroll
                for (int mt = 0; mt < 2; mt++) {
                    mma_f16(acc[mt][2 * np],     af[mt][0], af[mt][1], af[mt][2], af[mt][3], b00, b01);
                    mma_f16(acc[mt][2 * np + 1], af[mt][0], af[mt][1], af[mt][2], af[mt][3], b10, b11);
                }
            }
        }
        __syncthreads();
    }

    // ---- epilogue ----
    const int bIdx  = rowBase >> 11;
    const int tbase = rowBase & (Tt - 1);
    const int hIdx  = colBase >> 7;

    // Stage fp16 tile in smem (stride 136 halfs = 68 words)
#pragma unroll
    for (int mt = 0; mt < 2; mt++) {
#pragma unroll
        for (int nt = 0; nt < 8; nt++) {
            const int r0 = wm + mt * 16 + gid;
            const int cw = ((wn + nt * 8) >> 1) + tig;
            ((uint32_t*)tile)[r0 * 68 + cw]       = packh2(acc[mt][nt][0], acc[mt][nt][1]);
            ((uint32_t*)tile)[(r0 + 8) * 68 + cw] = packh2(acc[mt][nt][2], acc[mt][nt][3]);
        }
    }
    __syncthreads();

    if (z == 2) {
        // V: transposed write, 16B-vector along t
        const int d = tid >> 1;
        const int tchunk = (tid & 1) * 64;
        __half* dst = vt + ((size_t)(bIdx * Hh + hIdx) * Dd + d) * Tt + tbase + tchunk;
#pragma unroll
        for (int j = 0; j < 64; j += 8) {
            __half vals[8];
#pragma unroll
            for (int u = 0; u < 8; u++)
                vals[u] = tile[(tchunk + j + u) * 136 + d];
            *(uint4*)(dst + j) = *(uint4*)vals;
        }
        return;
    }

    // Q/K: 2 lanes per row; halfSel selects d-subset
    const int row = warp * 16 + (lane >> 1);
    const int halfSel = lane & 1;
    const int d0 = halfSel * 32;               // pairs (d0+j, d0+j+64)
    const __half* trow = tile + row * 136;

    float ssq = 0.f;
#pragma unroll
    for (int j = 0; j < 32; j += 8) {
        uint4 eu = *(const uint4*)(trow + d0 + j);
        uint4 ou = *(const uint4*)(trow + d0 + 64 + j);
        const uint32_t* ew = (const uint32_t*)&eu;
        const uint32_t* ow = (const uint32_t*)&ou;
#pragma unroll
        for (int w2 = 0; w2 < 4; w2++) {
            float2 e2 = __half22float2(*(const __half2*)&ew[w2]);
            float2 o2 = __half22float2(*(const __half2*)&ow[w2]);
            ssq += e2.x * e2.x + e2.y * e2.y + o2.x * o2.x + o2.y * o2.y;
        }
    }
    ssq += __shfl_xor_sync(0xffffffffu, ssq, 1);

    const float scale = rsqrtf(ssq * (1.0f / 128.0f) + 1e-6f) * 0.08838834764831845f;
    const int tg = tbase + row;
    const float4* rtab = rope + (size_t)tg * 32;
    __half* dst = ((z == 0) ? qh : kh) + ((size_t)(bIdx * Hh + hIdx) * Tt + tg) * Dd;

#pragma unroll
    for (int j = 0; j < 32; j += 8) {
        uint4 eu = *(const uint4*)(trow + d0 + j);
        uint4 ou = *(const uint4*)(trow + d0 + 64 + j);
        const uint32_t* ew = (const uint32_t*)&eu;
        const uint32_t* ow = (const uint32_t*)&ou;
        uint32_t outE[4], outO[4];
#pragma unroll
        for (int w2 = 0; w2 < 4; w2++) {
            float2 e2 = __half22float2(*(const __half2*)&ew[w2]);
            float2 o2 = __half22float2(*(const __half2*)&ow[w2]);
            const float4 cs = rtab[(d0 + j + w2 * 2) >> 1];   // cos0,sin0,cos1,sin1
            float ev0 = e2.x * scale, ov0 = o2.x * scale;
            float ev1 = e2.y * scale, ov1 = o2.y * scale;
            outE[w2] = packh2(ev0 * cs.x - ov0 * cs.y, ev1 * cs.z - ov1 * cs.w);
            outO[w2] = packh2(ev0 * cs.y + ov0 * cs.x, ev1 * cs.w + ov1 * cs.z);
        }
        *(uint4*)(dst + d0 + j)      = *(uint4*)outE;
        *(uint4*)(dst + d0 + 64 + j) = *(uint4*)outO;
    }
}

// ---------------------------------------------------------------------------
// FP16 GEMM for out-projection: C(fp32)[M,N] = A[M,K] * B^T[N,K].
// ---------------------------------------------------------------------------
__global__ __launch_bounds__(256, 2) void gemm_h(const __half* __restrict__ A,
                                                 const __half* __restrict__ Bt,
                                                 float* __restrict__ C,
                                                 int M, int N, int K) {
    __shared__ uint32_t As[2][GW];
    __shared__ uint32_t Bs[2][GW];

    const int tid  = threadIdx.x;
    const int lane = tid & 31;
    const int warp = tid >> 5;
    const int gid  = lane >> 2;
    const int tig  = lane & 3;
    const int lm   = lane >> 3;
    const int lr   = lane & 7;
    const int wm   = (warp >> 1) * 32;
    const int wn   = (warp & 1) * 64;
    const int rowBase = blockIdx.y * 128;
    const int colBase = blockIdx.x * 128;

    const __half* Ag = A + (size_t)rowBase * K;
    const __half* Bg = Bt + (size_t)colBase * K;
    const uint32_t sA = (uint32_t)__cvta_generic_to_shared(&As[0][0]);
    const uint32_t sB = (uint32_t)__cvta_generic_to_shared(&Bs[0][0]);

    float acc[2][8][4];
#pragma unroll
    for (int mt = 0; mt < 2; mt++)
#pragma unroll
        for (int nt = 0; nt < 8; nt++)
#pragma unroll
            for (int i = 0; i < 4; i++) acc[mt][nt][i] = 0.f;

    {
#pragma unroll
        for (int i = 0; i < 2; i++) {
            const int s = tid + i * 256;
            const int r = s >> 2, c = s & 3;
            cp16(sA + (r * HGSTR + c * 4) * 4, Ag + (size_t)r * K + c * 8);
            cp16(sB + (r * HGSTR + c * 4) * 4, Bg + (size_t)r * K + c * 8);
        }
        CP_COMMIT();
    }

    const int niter = K >> 5;
    for (int it = 0; it < niter; it++) {
        const int cur = it & 1;
        if (it + 1 < niter) {
            const int k0 = (it + 1) << 5;
            const int nxt = (it + 1) & 1;
#pragma unroll
            for (int i = 0; i < 2; i++) {
                const int s = tid + i * 256;
                const int r = s >> 2, c = s & 3;
                cp16(sA + (nxt * GW + r * HGSTR + c * 4) * 4,
                     Ag + (size_t)r * K + k0 + c * 8);
                cp16(sB + (nxt * GW + r * HGSTR + c * 4) * 4,
                     Bg + (size_t)r * K + k0 + c * 8);
            }
            CP_COMMIT();
            CP_WAIT(1);
        } else {
            CP_WAIT(0);
        }
        __syncthreads();

        const uint32_t sAc = sA + cur * GW * 4;
        const uint32_t sBc = sB + cur * GW * 4;
#pragma unroll
        for (int kh2 = 0; kh2 < 2; kh2++) {
            const int kk = kh2 * 8;
            uint32_t af[2][4];
#pragma unroll
            for (int mt = 0; mt < 2; mt++) {
                const int row = wm + mt * 16 + (lm & 1) * 8 + lr;
                const int word = kk + (lm >> 1) * 4;
                ldsm4(af[mt][0], af[mt][1], af[mt][2], af[mt][3],
                      sAc + (row * HGSTR + word) * 4);
            }
#pragma unroll
            for (int np = 0; np < 4; np++) {
                const int row = wn + (2 * np + (lm >> 1)) * 8 + lr;
                const int word = kk + (lm & 1) * 4;
                uint32_t b00, b01, b10, b11;
                ldsm4(b00, b01, b10, b11, sBc + (row * HGSTR + word) * 4);
#pragma unroll
                for (int mt = 0; mt < 2; mt++) {
                    mma_f16(acc[mt][2 * np],     af[mt][0], af[mt][1], af[mt][2], af[mt][3], b00, b01);
                    mma_f16(acc[mt][2 * np + 1], af[mt][0], af[mt][1], af[mt][2], af[mt][3], b10, b11);
                }
            }
        }
        __syncthreads();
    }

#pragma unroll
    for (int mt = 0; mt < 2; mt++) {
#pragma unroll
        for (int nt = 0; nt < 8; nt++) {
            const int r0 = rowBase + wm + mt * 16 + gid;
            const int c0 = colBase + wn + nt * 8 + 2 * tig;
            *(float2*)(C + (size_t)r0 * N + c0)       = make_float2(acc[mt][nt][0], acc[mt][nt][1]);
            *(float2*)(C + (size_t)(r0 + 8) * N + c0) = make_float2(acc[mt][nt][2], acc[mt][nt][3]);
        }
    }
}

// ---------------------------------------------------------------------------
// FP16 flash attention (causal), LDSM operands: BR=64 (4 warps), BC=64.
// ---------------------------------------------------------------------------
#define BRt 64
#define BCt 64
#define HKSTR 68
#define HVSTR 36
#define HOFF_K0 0
#define HOFF_V0 (HOFF_K0 + 64*HKSTR)    // 4352
#define HOFF_K1 (HOFF_V0 + 128*HVSTR)   // 8960
#define HOFF_V1 (HOFF_K1 + 64*HKSTR)    // 13312
#define HSM_WORDS (HOFF_V1 + 128*HVSTR) // 17920 words = 71680 B

__global__ __launch_bounds__(128, 3) void attn_h(const __half* __restrict__ qh,
                                                 const __half* __restrict__ kh,
                                                 const __half* __restrict__ vt,
                                                 __half* __restrict__ oh) {
    extern __shared__ uint32_t smu[];

    const int tid  = threadIdx.x;
    const int lane = tid & 31;
    const int warp = tid >> 5;
    const int gid  = lane >> 2;
    const int tig  = lane & 3;
    const int lm   = lane >> 3;
    const int lr   = lane & 7;
    const int qb = (gridDim.x - 1) - blockIdx.x;   // heavy blocks first
    const int h = blockIdx.y, b = blockIdx.z;
    const int t0 = qb * BRt;
    const int wrow = warp * 16;

    const size_t bhOff = (size_t)(b * Hh + h) * Tt * Dd;
    const __half* qbase = qh + bhOff + (size_t)t0 * Dd;
    const __half* kbase = kh + bhOff;
    const __half* vbase = vt + bhOff;              // [d][t]
    const uint32_t smemBase = (uint32_t)__cvta_generic_to_shared(smu);

    const int bRowSel = lm >> 1;
    const int bKSel   = lm & 1;

    {
#pragma unroll
        for (int i = 0; i < 8; i++) {
            const int s = tid + i * 128;
            const int r = s >> 4, c = s & 15;
            cp16(smemBase + (HOFF_K0 + r * HKSTR + c * 4) * 4,
                 kbase + (size_t)r * Dd + c * 8);
        }
#pragma unroll
        for (int i = 0; i < 8; i++) {
            const int s = tid + i * 128;
            const int r = s >> 3, c = s & 7;
            cp16(smemBase + (HOFF_V0 + r * HVSTR + c * 4) * 4,
                 vbase + (size_t)r * Tt + c * 8);
        }
        CP_COMMIT();
    }
    {
#pragma unroll
        for (int i = 0; i < 8; i++) {
            const int s = tid + i * 128;
            const int r = s >> 4, c = s & 15;
            cp16(smemBase + (HOFF_K1 + r * HKSTR + c * 4) * 4,
                 qbase + (size_t)r * Dd + c * 8);
        }
        CP_COMMIT();
        CP_WAIT(0);
    }
    __syncthreads();

    uint32_t qf[8][4];
    {
        const uint32_t qRow = wrow + (lm & 1) * 8 + lr;
        const uint32_t qWordSel = (lm >> 1) * 4;
#pragma unroll
        for (int ks = 0; ks < 8; ks++) {
            ldsm4(qf[ks][0], qf[ks][1], qf[ks][2], qf[ks][3],
                  smemBase + (HOFF_K1 + qRow * HKSTR + 8 * ks + qWordSel) * 4);
        }
    }
    __syncthreads();

    float m0 = -1e30f, m1 = -1e30f, l0 = 0.f, l1 = 0.f;
    float oacc[16][4];
#pragma unroll
    for (int nt = 0; nt < 16; nt++)
#pragma unroll
        for (int i = 0; i < 4; i++) oacc[nt][i] = 0.f;

    for (int kb = 0; kb <= qb; kb++) {
        if (kb + 1 <= qb) {
            const int tk0 = (kb + 1) * BCt;
            const int offK = ((kb + 1) & 1) ? HOFF_K1 : HOFF_K0;
            const int offV = ((kb + 1) & 1) ? HOFF_V1 : HOFF_V0;
#pragma unroll
            for (int i = 0; i < 8; i++) {
                const int s = tid + i * 128;
                const int r = s >> 4, c = s & 15;
                cp16(smemBase + (offK + r * HKSTR + c * 4) * 4,
                     kbase + (size_t)(tk0 + r) * Dd + c * 8);
            }
#pragma unroll
            for (int i = 0; i < 8; i++) {
                const int s = tid + i * 128;
                const int r = s >> 3, c = s & 7;
                cp16(smemBase + (offV + r * HVSTR + c * 4) * 4,
                     vbase + (size_t)r * Tt + tk0 + c * 8);
            }
            CP_COMMIT();
            CP_WAIT(1);
        } else {
            CP_WAIT(0);
        }
        __syncthreads();

        const uint32_t offK = (kb & 1) ? HOFF_K1 : HOFF_K0;
        const uint32_t offV = (kb & 1) ? HOFF_V1 : HOFF_V0;
        const int tk0 = kb * BCt;

        float sacc[8][4];
#pragma unroll
        for (int nt = 0; nt < 8; nt++)
#pragma unroll
            for (int i = 0; i < 4; i++) sacc[nt][i] = 0.f;

        const uint32_t kAddr0 = smemBase + (offK + ((bRowSel * 8 + lr) * HKSTR) + bKSel * 4) * 4;
#pragma unroll
        for (int ks = 0; ks < 8; ks++) {
#pragma unroll
            for (int np = 0; np < 4; np++) {
                uint32_t b00, b01, b10, b11;
                ldsm4(b00, b01, b10, b11,
                      kAddr0 + ((2 * np) * 8 * HKSTR + 8 * ks) * 4);
                mma_f16(sacc[2 * np],     qf[ks][0], qf[ks][1], qf[ks][2], qf[ks][3], b00, b01);
                mma_f16(sacc[2 * np + 1], qf[ks][0], qf[ks][1], qf[ks][2], qf[ks][3], b10, b11);
            }
        }

        if (kb == qb) {
            const int rg0 = t0 + wrow + gid;
            const int rg1 = rg0 + 8;
#pragma unroll
            for (int nt = 0; nt < 8; nt++) {
                const int cg = tk0 + nt * 8 + 2 * tig;
                if (rg0 < cg)     sacc[nt][0] = -1e30f;
                if (rg0 < cg + 1) sacc[nt][1] = -1e30f;
                if (rg1 < cg)     sacc[nt][2] = -1e30f;
                if (rg1 < cg + 1) sacc[nt][3] = -1e30f;
            }
        }

        float rm0 = -1e30f, rm1 = -1e30f;
#pragma unroll
        for (int nt = 0; nt < 8; nt++) {
            rm0 = fmaxf(rm0, fmaxf(sacc[nt][0], sacc[nt][1]));
            rm1 = fmaxf(rm1, fmaxf(sacc[nt][2], sacc[nt][3]));
        }
        rm0 = fmaxf(rm0, __shfl_xor_sync(0xffffffffu, rm0, 1));
        rm0 = fmaxf(rm0, __shfl_xor_sync(0xffffffffu, rm0, 2));
        rm1 = fmaxf(rm1, __shfl_xor_sync(0xffffffffu, rm1, 1));
        rm1 = fmaxf(rm1, __shfl_xor_sync(0xffffffffu, rm1, 2));

        const float nm0 = fmaxf(m0, rm0);
        const float nm1 = fmaxf(m1, rm1);
        float sum0 = 0.f, sum1 = 0.f;
        uint32_t pe[8][2];
#pragma unroll
        for (int nt = 0; nt < 8; nt++) {
            float e00 = __expf(sacc[nt][0] - nm0);
            float e01 = __expf(sacc[nt][1] - nm0);
            float e10 = __expf(sacc[nt][2] - nm1);
            float e11 = __expf(sacc[nt][3] - nm1);
            sum0 += e00 + e01;
            sum1 += e10 + e11;
            pe[nt][0] = packh2(e00, e01);
            pe[nt][1] = packh2(e10, e11);
        }
        sum0 += __shfl_xor_sync(0xffffffffu, sum0, 1);
        sum0 += __shfl_xor_sync(0xffffffffu, sum0, 2);
        sum1 += __shfl_xor_sync(0xffffffffu, sum1, 1);
        sum1 += __shfl_xor_sync(0xffffffffu, sum1, 2);

        const float c0 = __expf(m0 - nm0);
        const float c1 = __expf(m1 - nm1);
        l0 = l0 * c0 + sum0; m0 = nm0;
        l1 = l1 * c1 + sum1; m1 = nm1;
#pragma unroll
        for (int nt = 0; nt < 16; nt++) {
            oacc[nt][0] *= c0; oacc[nt][1] *= c0;
            oacc[nt][2] *= c1; oacc[nt][3] *= c1;
        }

        const uint32_t vAddr0 = smemBase + (offV + ((bRowSel * 8 + lr) * HVSTR) + bKSel * 4) * 4;
#pragma unroll
        for (int ks = 0; ks < 4; ks++) {
            const uint32_t a0 = pe[2 * ks][0];
            const uint32_t a1 = pe[2 * ks][1];
            const uint32_t a2 = pe[2 * ks + 1][0];
            const uint32_t a3 = pe[2 * ks + 1][1];
#pragma unroll
            for (int np = 0; np < 8; np++) {
                uint32_t b00, b01, b10, b11;
                ldsm4(b00, b01, b10, b11,
                      vAddr0 + ((2 * np) * 8 * HVSTR + 8 * ks) * 4);
                mma_f16(oacc[2 * np],     a0, a1, a2, a3, b00, b01);
                mma_f16(oacc[2 * np + 1], a0, a1, a2, a3, b10, b11);
            }
        }
        __syncthreads();
    }

    const float i0 = 1.0f / l0;
    const float i1 = 1.0f / l1;
    const int rg0 = t0 + wrow + gid;
    __half* ob0 = oh + ((size_t)(b * Tt + rg0) * Hh + h) * Dd;
    __half* ob1 = oh + ((size_t)(b * Tt + rg0 + 8) * Hh + h) * Dd;
#pragma unroll
    for (int nt = 0; nt < 16; nt++) {
        const int col = nt * 8 + 2 * tig;
        *(uint32_t*)(ob0 + col) = packh2(oacc[nt][0] * i0, oacc[nt][1] * i0);
        *(uint32_t*)(ob1 + col) = packh2(oacc[nt][2] * i1, oacc[nt][3] * i1);
    }
}

// ---------------------------------------------------------------------------
extern "C" void kernel_launch(void* const* d_in, const int* in_sizes, int n_in,
                              void* d_out, int out_size) {
    const float* x  = (const float*)d_in[0];
    const float* wq = (const float*)d_in[1];
    const float* wk = (const float*)d_in[2];
    const float* wv = (const float*)d_in[3];
    const float* wo = (const float*)d_in[4];
    float* out = (float*)d_out;

    __half *xh, *wqt, *wkt, *wvt, *wot, *qhp, *khp, *vtp, *ohp;
    float4* ropeTab;
    cudaGetSymbolAddress((void**)&xh, g_xh);
    cudaGetSymbolAddress((void**)&wqt, g_wqt);
    cudaGetSymbolAddress((void**)&wkt, g_wkt);
    cudaGetSymbolAddress((void**)&wvt, g_wvt);
    cudaGetSymbolAddress((void**)&wot, g_wot);
    cudaGetSymbolAddress((void**)&qhp, g_qh);
    cudaGetSymbolAddress((void**)&khp, g_kh);
    cudaGetSymbolAddress((void**)&vtp, g_vt);
    cudaGetSymbolAddress((void**)&ohp, g_oh);
    cudaGetSymbolAddress((void**)&ropeTab, g_rope);

    // Convert x; transpose+convert weights; build RoPE table
    f2h<<<(BT*Mm/4 + 255)/256, 256>>>(x, xh, BT*Mm/4);
    wtrans<<<dim3(32, 32, 4), dim3(32, 8)>>>(wq, wk, wv, wo, wqt, wkt, wvt, wot);
    rope_init<<<(Tt*32 + 255)/256, 256>>>(ropeTab);

    // Fused QKV projections + RMSNorm/RoPE (q,k) + transpose (v)
    dim3 gp(HD / 128, BT / 128, 3);
    gemm_qkv<<<gp, 256>>>(xh, wqt, wkt, wvt, qhp, khp, vtp, ropeTab);

    // FP16 flash attention -> fp16 O [b,t,h,d]
    size_t smem = (size_t)HSM_WORDS * 4;
    cudaFuncSetAttribute(attn_h, cudaFuncAttributeMaxDynamicSharedMemorySize, (int)smem);
    dim3 ga(Tt / BRt, Hh, Bq);
    attn_h<<<ga, 128, smem>>>(qhp, khp, vtp, ohp);

    // Output projection -> fp32 out
    dim3 go(Mm / 128, BT / 128);
    gemm_h<<<go, 256>>>(ohp, wot, out, BT, Mm, HD);
}

// round 14
// speedup vs baseline: 1.1991x; 1.1991x over previous
#include <cuda_runtime.h>
#include <cuda_fp16.h>
#include <math.h>
#include <stdint.h>

// Problem dims (fixed)
#define Bq 2
#define Tt 2048
#define Mm 1024
#define Hh 8
#define Dd 128
#define BT (Bq*Tt)      // 4096
#define HD (Hh*Dd)      // 1024

// Scratch — no cudaMalloc allowed
__device__ __half g_xh[BT*Mm];         // fp16 x
__device__ __half g_wqt[Mm*HD];        // fp16 wq^T [N][K]
__device__ __half g_wkt[Mm*HD];
__device__ __half g_wvt[Mm*HD];
__device__ __half g_wot[HD*Mm];        // fp16 wo^T [N=Mm][K=HD]
__device__ __half g_qh[BT*HD];         // fp16 q (normed/roped) [b,h,t,d]
__device__ __half g_kh[BT*HD];         // fp16 k [b,h,t,d]
__device__ __half g_vt[BT*HD];         // fp16 v transposed [b,h,d,t]
__device__ __half g_oh[BT*HD];         // fp16 attention out [b,t,h,d]

__device__ __forceinline__ void mma_f16(float c[4], uint32_t a0, uint32_t a1,
                                        uint32_t a2, uint32_t a3,
                                        uint32_t b0, uint32_t b1) {
    asm volatile(
        "mma.sync.aligned.m16n8k16.row.col.f32.f16.f16.f32 "
        "{%0,%1,%2,%3}, {%4,%5,%6,%7}, {%8,%9}, {%0,%1,%2,%3};\n"
        : "+f"(c[0]), "+f"(c[1]), "+f"(c[2]), "+f"(c[3])
        : "r"(a0), "r"(a1), "r"(a2), "r"(a3), "r"(b0), "r"(b1));
}

__device__ __forceinline__ void ldsm4(uint32_t& r0, uint32_t& r1,
                                      uint32_t& r2, uint32_t& r3, uint32_t addr) {
    asm volatile("ldmatrix.sync.aligned.m8n8.x4.shared.b16 {%0,%1,%2,%3}, [%4];"
                 : "=r"(r0), "=r"(r1), "=r"(r2), "=r"(r3) : "r"(addr));
}

__device__ __forceinline__ uint32_t packh2(float lo, float hi) {
    __half2 h = __floats2half2_rn(lo, hi);
    return *(uint32_t*)&h;
}

__device__ __forceinline__ void cp16(uint32_t dst, const void* src) {
    asm volatile("cp.async.ca.shared.global [%0], [%1], 16;\n" :: "r"(dst), "l"(src));
}
#define CP_COMMIT() asm volatile("cp.async.commit_group;\n" ::: "memory")
#define CP_WAIT(n)  asm volatile("cp.async.wait_group %0;\n" :: "n"(n) : "memory")

// ---------------------------------------------------------------------------
__global__ __launch_bounds__(256) void f2h(const float* __restrict__ src,
                                           __half* __restrict__ dst, int n4) {
    int i = blockIdx.x * blockDim.x + threadIdx.x;
    if (i < n4) {
        float4 v = ((const float4*)src)[i];
        ((uint2*)dst)[i] = make_uint2(packh2(v.x, v.y), packh2(v.z, v.w));
    }
}

// ---------------------------------------------------------------------------
// Weight transpose + fp16: w [1024][1024] fp32 -> wt fp16 (w^T). z: which.
// ---------------------------------------------------------------------------
__global__ __launch_bounds__(256) void wtrans(const float* __restrict__ w0,
                                              const float* __restrict__ w1,
                                              const float* __restrict__ w2,
                                              const float* __restrict__ w3,
                                              __half* __restrict__ o0,
                                              __half* __restrict__ o1,
                                              __half* __restrict__ o2,
                                              __half* __restrict__ o3) {
    const float* w = (blockIdx.z == 0) ? w0 : (blockIdx.z == 1) ? w1
                     : (blockIdx.z == 2) ? w2 : w3;
    __half* o = (blockIdx.z == 0) ? o0 : (blockIdx.z == 1) ? o1
                : (blockIdx.z == 2) ? o2 : o3;
    __shared__ __half tile[32][33];
    const int tx = threadIdx.x, ty = threadIdx.y;
    const int k0 = blockIdx.x * 32, n0 = blockIdx.y * 32;
#pragma unroll
    for (int i = 0; i < 4; i++)
        tile[ty + i * 8][tx] = __float2half_rn(w[(size_t)(k0 + ty + i * 8) * 1024 + n0 + tx]);
    __syncthreads();
#pragma unroll
    for (int i = 0; i < 4; i++)
        o[(size_t)(n0 + ty + i * 8) * 1024 + k0 + tx] = tile[tx][ty + i * 8];
}

// ---------------------------------------------------------------------------
// Fused QKV GEMM v2: 128x128 CTA tile, BK=32, 128 threads (4 warps, 64x64
// warp tiles -> MMA/LDSM ratio 4.0 vs 2.67). Per-head epilogue:
// z=0: q -> RMSNorm+RoPE -> g_qh [b,h,t,d]
// z=1: k -> RMSNorm+RoPE -> g_kh [b,h,t,d]
// z=2: v -> transposed scatter -> g_vt [b,h,d,t]
// ---------------------------------------------------------------------------
#define HGSTR 20
#define GW (128*HGSTR)   // 2560 words per buffer

__global__ __launch_bounds__(128, 2) void gemm_qkv(const __half* __restrict__ A,
                                                   const __half* __restrict__ B0,
                                                   const __half* __restrict__ B1,
                                                   const __half* __restrict__ B2,
                                                   __half* __restrict__ qh,
                                                   __half* __restrict__ kh,
                                                   __half* __restrict__ vt) {
    const int z = blockIdx.z;
    const __half* Bt = (z == 0) ? B0 : (z == 1) ? B1 : B2;

    __shared__ uint32_t smx[4 * GW];            // As[2] | Bs[2]; aliased by tile
    uint32_t* sAb = smx;
    uint32_t* sBb = smx + 2 * GW;
    __half*   tile = (__half*)smx;              // epilogue: [128][136] halfs

    const int tid  = threadIdx.x;
    const int lane = tid & 31;
    const int warp = tid >> 5;
    const int gid  = lane >> 2;
    const int tig  = lane & 3;
    const int lm   = lane >> 3;
    const int lr   = lane & 7;
    const int wm   = (warp >> 1) * 64;
    const int wn   = (warp & 1) * 64;
    const int rowBase = blockIdx.y * 128;
    const int colBase = blockIdx.x * 128;
    const int K = Mm;

    const __half* Ag = A + (size_t)rowBase * K;
    const __half* Bg = Bt + (size_t)colBase * K;
    const uint32_t sA = (uint32_t)__cvta_generic_to_shared(sAb);
    const uint32_t sB = (uint32_t)__cvta_generic_to_shared(sBb);

    float acc[4][8][4];
#pragma unroll
    for (int mt = 0; mt < 4; mt++)
#pragma unroll
        for (int nt = 0; nt < 8; nt++)
#pragma unroll
            for (int i = 0; i < 4; i++) acc[mt][nt][i] = 0.f;

    {
#pragma unroll
        for (int i = 0; i < 4; i++) {
            const int s = tid + i * 128;
            const int r = s >> 2, c = s & 3;
            cp16(sA + (r * HGSTR + c * 4) * 4, Ag + (size_t)r * K + c * 8);
            cp16(sB + (r * HGSTR + c * 4) * 4, Bg + (size_t)r * K + c * 8);
        }
        CP_COMMIT();
    }

    const int niter = K >> 5;
    for (int it = 0; it < niter; it++) {
        const int cur = it & 1;
        if (it + 1 < niter) {
            const int k0 = (it + 1) << 5;
            const int nxt = (it + 1) & 1;
#pragma unroll
            for (int i = 0; i < 4; i++) {
                const int s = tid + i * 128;
                const int r = s >> 2, c = s & 3;
                cp16(sA + (nxt * GW + r * HGSTR + c * 4) * 4,
                     Ag + (size_t)r * K + k0 + c * 8);
                cp16(sB + (nxt * GW + r * HGSTR + c * 4) * 4,
                     Bg + (size_t)r * K + k0 + c * 8);
            }
            CP_COMMIT();
            CP_WAIT(1);
        } else {
            CP_WAIT(0);
        }
        __syncthreads();

        const uint32_t sAc = sA + cur * GW * 4;
        const uint32_t sBc = sB + cur * GW * 4;
#pragma unroll
        for (int kh2 = 0; kh2 < 2; kh2++) {
            const int kk = kh2 * 8;
            uint32_t af[4][4];
#pragma unroll
            for (int mt = 0; mt < 4; mt++) {
                const int row = wm + mt * 16 + (lm & 1) * 8 + lr;
                const int word = kk + (lm >> 1) * 4;
                ldsm4(af[mt][0], af[mt][1], af[mt][2], af[mt][3],
                      sAc + (row * HGSTR + word) * 4);
            }
#pragma unroll
            for (int np = 0; np < 4; np++) {
                const int row = wn + (2 * np + (lm >> 1)) * 8 + lr;
                const int word = kk + (lm & 1) * 4;
                uint32_t b00, b01, b10, b11;
                ldsm4(b00, b01, b10, b11, sBc + (row * HGSTR + word) * 4);
#pragma unroll
                for (int mt = 0; mt < 4; mt++) {
                    mma_f16(acc[mt][2 * np],     af[mt][0], af[mt][1], af[mt][2], af[mt][3], b00, b01);
                    mma_f16(acc[mt][2 * np + 1], af[mt][0], af[mt][1], af[mt][2], af[mt][3], b10, b11);
                }
            }
        }
        __syncthreads();
    }

    // ---- epilogue ----
    const int bIdx  = rowBase >> 11;
    const int tbase = rowBase & (Tt - 1);
    const int hIdx  = colBase >> 7;

    if (z == 2) {
        // V: direct transposed scatter to [b,h,d,t] (r11-proven behavior)
        __half* dst = vt + ((size_t)(bIdx * Hh + hIdx) * Dd) * Tt;
#pragma unroll
        for (int mt = 0; mt < 4; mt++) {
#pragma unroll
            for (int nt = 0; nt < 8; nt++) {
                const int r0 = wm + mt * 16 + gid;
                const int c0 = wn + nt * 8 + 2 * tig;
                const int tg = tbase + r0;
                dst[(size_t)c0 * Tt + tg]           = __float2half_rn(acc[mt][nt][0]);
                dst[(size_t)(c0 + 1) * Tt + tg]     = __float2half_rn(acc[mt][nt][1]);
                dst[(size_t)c0 * Tt + tg + 8]       = __float2half_rn(acc[mt][nt][2]);
                dst[(size_t)(c0 + 1) * Tt + tg + 8] = __float2half_rn(acc[mt][nt][3]);
            }
        }
        return;
    }

    // Q/K: stage fp16 tile in smem (stride 136 halfs = 68 words)
#pragma unroll
    for (int mt = 0; mt < 4; mt++) {
#pragma unroll
        for (int nt = 0; nt < 8; nt++) {
            const int r0 = wm + mt * 16 + gid;
            const int cw = ((wn + nt * 8) >> 1) + tig;
            ((uint32_t*)tile)[r0 * 68 + cw]       = packh2(acc[mt][nt][0], acc[mt][nt][1]);
            ((uint32_t*)tile)[(r0 + 8) * 68 + cw] = packh2(acc[mt][nt][2], acc[mt][nt][3]);
        }
    }
    __syncthreads();

    // 1 thread per row (128 threads, 128 rows); full-row RMSNorm, inline RoPE
    const int row = tid;
    const __half* trow = tile + row * 136;

    float ssq = 0.f;
#pragma unroll
    for (int j = 0; j < 64; j += 8) {
        uint4 eu = *(const uint4*)(trow + j);
        uint4 ou = *(const uint4*)(trow + 64 + j);
        const uint32_t* ew = (const uint32_t*)&eu;
        const uint32_t* ow = (const uint32_t*)&ou;
#pragma unroll
        for (int w2 = 0; w2 < 4; w2++) {
            float2 e2 = __half22float2(*(const __half2*)&ew[w2]);
            float2 o2 = __half22float2(*(const __half2*)&ow[w2]);
            ssq += e2.x * e2.x + e2.y * e2.y + o2.x * o2.x + o2.y * o2.y;
        }
    }

    const float scale = rsqrtf(ssq * (1.0f / 128.0f) + 1e-6f) * 0.08838834764831845f;
    const int tg = tbase + row;
    const float c64 = -0.20762050593017578f;   // -log2(10000)/64
    __half* dst = ((z == 0) ? qh : kh) + ((size_t)(bIdx * Hh + hIdx) * Tt + tg) * Dd;

#pragma unroll
    for (int j = 0; j < 64; j += 8) {
        uint4 eu = *(const uint4*)(trow + j);
        uint4 ou = *(const uint4*)(trow + 64 + j);
        const uint32_t* ew = (const uint32_t*)&eu;
        const uint32_t* ow = (const uint32_t*)&ou;
        uint32_t outE[4], outO[4];
#pragma unroll
        for (int w2 = 0; w2 < 4; w2++) {
            float2 e2 = __half22float2(*(const __half2*)&ew[w2]);
            float2 o2 = __half22float2(*(const __half2*)&ow[w2]);
            float re[2], ro[2];
#pragma unroll
            for (int u = 0; u < 2; u++) {
                const int i = j + w2 * 2 + u;
                float f = exp2f((float)i * c64);
                float sn, cs;
                __sincosf((float)tg * f, &sn, &cs);
                float ev = (u ? e2.y : e2.x) * scale;
                float ov = (u ? o2.y : o2.x) * scale;
                re[u] = ev * cs - ov * sn;
                ro[u] = ev * sn + ov * cs;
            }
            outE[w2] = packh2(re[0], re[1]);
            outO[w2] = packh2(ro[0], ro[1]);
        }
        *(uint4*)(dst + j)      = *(uint4*)outE;
        *(uint4*)(dst + 64 + j) = *(uint4*)outO;
    }
}

// ---------------------------------------------------------------------------
// FP16 GEMM v2 for out-projection: C(fp32)[M,N] = A[M,K] * B^T[N,K].
// Same 4-warp 64x64 warp-tile structure.
// ---------------------------------------------------------------------------
__global__ __launch_bounds__(128, 2) void gemm_h(const __half* __restrict__ A,
                                                 const __half* __restrict__ Bt,
                                                 float* __restrict__ C,
                                                 int M, int N, int K) {
    __shared__ uint32_t As[2][GW];
    __shared__ uint32_t Bs[2][GW];

    const int tid  = threadIdx.x;
    const int lane = tid & 31;
    const int warp = tid >> 5;
    const int gid  = lane >> 2;
    const int tig  = lane & 3;
    const int lm   = lane >> 3;
    const int lr   = lane & 7;
    const int wm   = (warp >> 1) * 64;
    const int wn   = (warp & 1) * 64;
    const int rowBase = blockIdx.y * 128;
    const int colBase = blockIdx.x * 128;

    const __half* Ag = A + (size_t)rowBase * K;
    const __half* Bg = Bt + (size_t)colBase * K;
    const uint32_t sA = (uint32_t)__cvta_generic_to_shared(&As[0][0]);
    const uint32_t sB = (uint32_t)__cvta_generic_to_shared(&Bs[0][0]);

    float acc[4][8][4];
#pragma unroll
    for (int mt = 0; mt < 4; mt++)
#pragma unroll
        for (int nt = 0; nt < 8; nt++)
#pragma unroll
            for (int i = 0; i < 4; i++) acc[mt][nt][i] = 0.f;

    {
#pragma unroll
        for (int i = 0; i < 4; i++) {
            const int s = tid + i * 128;
            const int r = s >> 2, c = s & 3;
            cp16(sA + (r * HGSTR + c * 4) * 4, Ag + (size_t)r * K + c * 8);
            cp16(sB + (r * HGSTR + c * 4) * 4, Bg + (size_t)r * K + c * 8);
        }
        CP_COMMIT();
    }

    const int niter = K >> 5;
    for (int it = 0; it < niter; it++) {
        const int cur = it & 1;
        if (it + 1 < niter) {
            const int k0 = (it + 1) << 5;
            const int nxt = (it + 1) & 1;
#pragma unroll
            for (int i = 0; i < 4; i++) {
                const int s = tid + i * 128;
                const int r = s >> 2, c = s & 3;
                cp16(sA + (nxt * GW + r * HGSTR + c * 4) * 4,
                     Ag + (size_t)r * K + k0 + c * 8);
                cp16(sB + (nxt * GW + r * HGSTR + c * 4) * 4,
                     Bg + (size_t)r * K + k0 + c * 8);
            }
            CP_COMMIT();
            CP_WAIT(1);
        } else {
            CP_WAIT(0);
        }
        __syncthreads();

        const uint32_t sAc = sA + cur * GW * 4;
        const uint32_t sBc = sB + cur * GW * 4;
#pragma unroll
        for (int kh2 = 0; kh2 < 2; kh2++) {
            const int kk = kh2 * 8;
            uint32_t af[4][4];
#pragma unroll
            for (int mt = 0; mt < 4; mt++) {
                const int row = wm + mt * 16 + (lm & 1) * 8 + lr;
                const int word = kk + (lm >> 1) * 4;
                ldsm4(af[mt][0], af[mt][1], af[mt][2], af[mt][3],
                      sAc + (row * HGSTR + word) * 4);
            }
#pragma unroll
            for (int np = 0; np < 4; np++) {
                const int row = wn + (2 * np + (lm >> 1)) * 8 + lr;
                const int word = kk + (lm & 1) * 4;
                uint32_t b00, b01, b10, b11;
                ldsm4(b00, b01, b10, b11, sBc + (row * HGSTR + word) * 4);
#pragma unroll
                for (int mt = 0; mt < 4; mt++) {
                    mma_f16(acc[mt][2 * np],     af[mt][0], af[mt][1], af[mt][2], af[mt][3], b00, b01);
                    mma_f16(acc[mt][2 * np + 1], af[mt][0], af[mt][1], af[mt][2], af[mt][3], b10, b11);
                }
            }
        }
        __syncthreads();
    }

#pragma unroll
    for (int mt = 0; mt < 4; mt++) {
#pragma unroll
        for (int nt = 0; nt < 8; nt++) {
            const int r0 = rowBase + wm + mt * 16 + gid;
            const int c0 = colBase + wn + nt * 8 + 2 * tig;
            *(float2*)(C + (size_t)r0 * N + c0)       = make_float2(acc[mt][nt][0], acc[mt][nt][1]);
            *(float2*)(C + (size_t)(r0 + 8) * N + c0) = make_float2(acc[mt][nt][2], acc[mt][nt][3]);
        }
    }
}

// ---------------------------------------------------------------------------
// FP16 flash attention (causal), LDSM operands: BR=64 (4 warps), BC=64.
// (unchanged from round 11 — best passing)
// ---------------------------------------------------------------------------
#define BRt 64
#define BCt 64
#define HKSTR 68
#define HVSTR 36
#define HOFF_K0 0
#define HOFF_V0 (HOFF_K0 + 64*HKSTR)
#define HOFF_K1 (HOFF_V0 + 128*HVSTR)
#define HOFF_V1 (HOFF_K1 + 64*HKSTR)
#define HSM_WORDS (HOFF_V1 + 128*HVSTR)

__global__ __launch_bounds__(128, 3) void attn_h(const __half* __restrict__ qh,
                                                 const __half* __restrict__ kh,
                                                 const __half* __restrict__ vt,
                                                 __half* __restrict__ oh) {
    extern __shared__ uint32_t smu[];

    const int tid  = threadIdx.x;
    const int lane = tid & 31;
    const int warp = tid >> 5;
    const int gid  = lane >> 2;
    const int tig  = lane & 3;
    const int lm   = lane >> 3;
    const int lr   = lane & 7;
    const int qb = (gridDim.x - 1) - blockIdx.x;
    const int h = blockIdx.y, b = blockIdx.z;
    const int t0 = qb * BRt;
    const int wrow = warp * 16;

    const size_t bhOff = (size_t)(b * Hh + h) * Tt * Dd;
    const __half* qbase = qh + bhOff + (size_t)t0 * Dd;
    const __half* kbase = kh + bhOff;
    const __half* vbase = vt + bhOff;
    const uint32_t smemBase = (uint32_t)__cvta_generic_to_shared(smu);

    const int bRowSel = lm >> 1;
    const int bKSel   = lm & 1;

    {
#pragma unroll
        for (int i = 0; i < 8; i++) {
            const int s = tid + i * 128;
            const int r = s >> 4, c = s & 15;
            cp16(smemBase + (HOFF_K0 + r * HKSTR + c * 4) * 4,
                 kbase + (size_t)r * Dd + c * 8);
        }
#pragma unroll
        for (int i = 0; i < 8; i++) {
            const int s = tid + i * 128;
            const int r = s >> 3, c = s & 7;
            cp16(smemBase + (HOFF_V0 + r * HVSTR + c * 4) * 4,
                 vbase + (size_t)r * Tt + c * 8);
        }
        CP_COMMIT();
    }
    {
#pragma unroll
        for (int i = 0; i < 8; i++) {
            const int s = tid + i * 128;
            const int r = s >> 4, c = s & 15;
            cp16(smemBase + (HOFF_K1 + r * HKSTR + c * 4) * 4,
                 qbase + (size_t)r * Dd + c * 8);
        }
        CP_COMMIT();
        CP_WAIT(0);
    }
    __syncthreads();

    uint32_t qf[8][4];
    {
        const uint32_t qRow = wrow + (lm & 1) * 8 + lr;
        const uint32_t qWordSel = (lm >> 1) * 4;
#pragma unroll
        for (int ks = 0; ks < 8; ks++) {
            ldsm4(qf[ks][0], qf[ks][1], qf[ks][2], qf[ks][3],
                  smemBase + (HOFF_K1 + qRow * HKSTR + 8 * ks + qWordSel) * 4);
        }
    }
    __syncthreads();

    float m0 = -1e30f, m1 = -1e30f, l0 = 0.f, l1 = 0.f;
    float oacc[16][4];
#pragma unroll
    for (int nt = 0; nt < 16; nt++)
#pragma unroll
        for (int i = 0; i < 4; i++) oacc[nt][i] = 0.f;

    for (int kb = 0; kb <= qb; kb++) {
        if (kb + 1 <= qb) {
            const int tk0 = (kb + 1) * BCt;
            const int offK = ((kb + 1) & 1) ? HOFF_K1 : HOFF_K0;
            const int offV = ((kb + 1) & 1) ? HOFF_V1 : HOFF_V0;
#pragma unroll
            for (int i = 0; i < 8; i++) {
                const int s = tid + i * 128;
                const int r = s >> 4, c = s & 15;
                cp16(smemBase + (offK + r * HKSTR + c * 4) * 4,
                     kbase + (size_t)(tk0 + r) * Dd + c * 8);
            }
#pragma unroll
            for (int i = 0; i < 8; i++) {
                const int s = tid + i * 128;
                const int r = s >> 3, c = s & 7;
                cp16(smemBase + (offV + r * HVSTR + c * 4) * 4,
                     vbase + (size_t)r * Tt + tk0 + c * 8);
            }
            CP_COMMIT();
            CP_WAIT(1);
        } else {
            CP_WAIT(0);
        }
        __syncthreads();

        const uint32_t offK = (kb & 1) ? HOFF_K1 : HOFF_K0;
        const uint32_t offV = (kb & 1) ? HOFF_V1 : HOFF_V0;
        const int tk0 = kb * BCt;

        float sacc[8][4];
#pragma unroll
        for (int nt = 0; nt < 8; nt++)
#pragma unroll
            for (int i = 0; i < 4; i++) sacc[nt][i] = 0.f;

        const uint32_t kAddr0 = smemBase + (offK + ((bRowSel * 8 + lr) * HKSTR) + bKSel * 4) * 4;
#pragma unroll
        for (int ks = 0; ks < 8; ks++) {
#pragma unroll
            for (int np = 0; np < 4; np++) {
                uint32_t b00, b01, b10, b11;
                ldsm4(b00, b01, b10, b11,
                      kAddr0 + ((2 * np) * 8 * HKSTR + 8 * ks) * 4);
                mma_f16(sacc[2 * np],     qf[ks][0], qf[ks][1], qf[ks][2], qf[ks][3], b00, b01);
                mma_f16(sacc[2 * np + 1], qf[ks][0], qf[ks][1], qf[ks][2], qf[ks][3], b10, b11);
            }
        }

        if (kb == qb) {
            const int rg0 = t0 + wrow + gid;
            const int rg1 = rg0 + 8;
#pragma unroll
            for (int nt = 0; nt < 8; nt++) {
                const int cg = tk0 + nt * 8 + 2 * tig;
                if (rg0 < cg)     sacc[nt][0] = -1e30f;
                if (rg0 < cg + 1) sacc[nt][1] = -1e30f;
                if (rg1 < cg)     sacc[nt][2] = -1e30f;
                if (rg1 < cg + 1) sacc[nt][3] = -1e30f;
            }
        }

        float rm0 = -1e30f, rm1 = -1e30f;
#pragma unroll
        for (int nt = 0; nt < 8; nt++) {
            rm0 = fmaxf(rm0, fmaxf(sacc[nt][0], sacc[nt][1]));
            rm1 = fmaxf(rm1, fmaxf(sacc[nt][2], sacc[nt][3]));
        }
        rm0 = fmaxf(rm0, __shfl_xor_sync(0xffffffffu, rm0, 1));
        rm0 = fmaxf(rm0, __shfl_xor_sync(0xffffffffu, rm0, 2));
        rm1 = fmaxf(rm1, __shfl_xor_sync(0xffffffffu, rm1, 1));
        rm1 = fmaxf(rm1, __shfl_xor_sync(0xffffffffu, rm1, 2));

        const float nm0 = fmaxf(m0, rm0);
        const float nm1 = fmaxf(m1, rm1);
        float sum0 = 0.f, sum1 = 0.f;
        uint32_t pe[8][2];
#pragma unroll
        for (int nt = 0; nt < 8; nt++) {
            float e00 = __expf(sacc[nt][0] - nm0);
            float e01 = __expf(sacc[nt][1] - nm0);
            float e10 = __expf(sacc[nt][2] - nm1);
            float e11 = __expf(sacc[nt][3] - nm1);
            sum0 += e00 + e01;
            sum1 += e10 + e11;
            pe[nt][0] = packh2(e00, e01);
            pe[nt][1] = packh2(e10, e11);
        }
        sum0 += __shfl_xor_sync(0xffffffffu, sum0, 1);
        sum0 += __shfl_xor_sync(0xffffffffu, sum0, 2);
        sum1 += __shfl_xor_sync(0xffffffffu, sum1, 1);
        sum1 += __shfl_xor_sync(0xffffffffu, sum1, 2);

        const float c0 = __expf(m0 - nm0);
        const float c1 = __expf(m1 - nm1);
        l0 = l0 * c0 + sum0; m0 = nm0;
        l1 = l1 * c1 + sum1; m1 = nm1;
#pragma unroll
        for (int nt = 0; nt < 16; nt++) {
            oacc[nt][0] *= c0; oacc[nt][1] *= c0;
            oacc[nt][2] *= c1; oacc[nt][3] *= c1;
        }

        const uint32_t vAddr0 = smemBase + (offV + ((bRowSel * 8 + lr) * HVSTR) + bKSel * 4) * 4;
#pragma unroll
        for (int ks = 0; ks < 4; ks++) {
            const uint32_t a0 = pe[2 * ks][0];
            const uint32_t a1 = pe[2 * ks][1];
            const uint32_t a2 = pe[2 * ks + 1][0];
            const uint32_t a3 = pe[2 * ks + 1][1];
#pragma unroll
            for (int np = 0; np < 8; np++) {
                uint32_t b00, b01, b10, b11;
                ldsm4(b00, b01, b10, b11,
                      vAddr0 + ((2 * np) * 8 * HVSTR + 8 * ks) * 4);
                mma_f16(oacc[2 * np],     a0, a1, a2, a3, b00, b01);
                mma_f16(oacc[2 * np + 1], a0, a1, a2, a3, b10, b11);
            }
        }
        __syncthreads();
    }

    const float i0 = 1.0f / l0;
    const float i1 = 1.0f / l1;
    const int rg0 = t0 + wrow + gid;
    __half* ob0 = oh + ((size_t)(b * Tt + rg0) * Hh + h) * Dd;
    __half* ob1 = oh + ((size_t)(b * Tt + rg0 + 8) * Hh + h) * Dd;
#pragma unroll
    for (int nt = 0; nt < 16; nt++) {
        const int col = nt * 8 + 2 * tig;
        *(uint32_t*)(ob0 + col) = packh2(oacc[nt][0] * i0, oacc[nt][1] * i0);
        *(uint32_t*)(ob1 + col) = packh2(oacc[nt][2] * i1, oacc[nt][3] * i1);
    }
}

// ---------------------------------------------------------------------------
extern "C" void kernel_launch(void* const* d_in, const int* in_sizes, int n_in,
                              void* d_out, int out_size) {
    const float* x  = (const float*)d_in[0];
    const float* wq = (const float*)d_in[1];
    const float* wk = (const float*)d_in[2];
    const float* wv = (const float*)d_in[3];
    const float* wo = (const float*)d_in[4];
    float* out = (float*)d_out;

    __half *xh, *wqt, *wkt, *wvt, *wot, *qhp, *khp, *vtp, *ohp;
    cudaGetSymbolAddress((void**)&xh, g_xh);
    cudaGetSymbolAddress((void**)&wqt, g_wqt);
    cudaGetSymbolAddress((void**)&wkt, g_wkt);
    cudaGetSymbolAddress((void**)&wvt, g_wvt);
    cudaGetSymbolAddress((void**)&wot, g_wot);
    cudaGetSymbolAddress((void**)&qhp, g_qh);
    cudaGetSymbolAddress((void**)&khp, g_kh);
    cudaGetSymbolAddress((void**)&vtp, g_vt);
    cudaGetSymbolAddress((void**)&ohp, g_oh);

    // Convert x; transpose+convert all four weights
    f2h<<<(BT*Mm/4 + 255)/256, 256>>>(x, xh, BT*Mm/4);
    wtrans<<<dim3(32, 32, 4), dim3(32, 8)>>>(wq, wk, wv, wo, wqt, wkt, wvt, wot);

    // Fused QKV projections + RMSNorm/RoPE (q,k) + transpose (v)
    dim3 gp(HD / 128, BT / 128, 3);
    gemm_qkv<<<gp, 128>>>(xh, wqt, wkt, wvt, qhp, khp, vtp);

    // FP16 flash attention -> fp16 O [b,t,h,d]
    size_t smem = (size_t)HSM_WORDS * 4;
    cudaFuncSetAttribute(attn_h, cudaFuncAttributeMaxDynamicSharedMemorySize, (int)smem);
    dim3 ga(Tt / BRt, Hh, Bq);
    attn_h<<<ga, 128, smem>>>(qhp, khp, vtp, ohp);

    // Output projection -> fp32 out
    dim3 go(Mm / 128, BT / 128);
    gemm_h<<<go, 128>>>(ohp, wot, out, BT, Mm, HD);
}

// round 15
// speedup vs baseline: 1.2090x; 1.0082x over previous
#include <cuda_runtime.h>
#include <cuda_fp16.h>
#include <math.h>
#include <stdint.h>

// Problem dims (fixed)
#define Bq 2
#define Tt 2048
#define Mm 1024
#define Hh 8
#define Dd 128
#define BT (Bq*Tt)      // 4096
#define HD (Hh*Dd)      // 1024

// Scratch — no cudaMalloc allowed
__device__ __half g_xh[BT*Mm];         // fp16 x
__device__ __half g_wqt[Mm*HD];        // fp16 wq^T [N][K]
__device__ __half g_wkt[Mm*HD];
__device__ __half g_wvt[Mm*HD];
__device__ __half g_wot[HD*Mm];        // fp16 wo^T [N=Mm][K=HD]
__device__ __half g_qh[BT*HD];         // fp16 q (normed/roped) [b,h,t,d]
__device__ __half g_kh[BT*HD];         // fp16 k [b,h,t,d]
__device__ __half g_vt[BT*HD];         // fp16 v transposed [b,h,d,t]
__device__ __half g_oh[BT*HD];         // fp16 attention out [b,t,h,d]

__device__ __forceinline__ void mma_f16(float c[4], uint32_t a0, uint32_t a1,
                                        uint32_t a2, uint32_t a3,
                                        uint32_t b0, uint32_t b1) {
    asm volatile(
        "mma.sync.aligned.m16n8k16.row.col.f32.f16.f16.f32 "
        "{%0,%1,%2,%3}, {%4,%5,%6,%7}, {%8,%9}, {%0,%1,%2,%3};\n"
        : "+f"(c[0]), "+f"(c[1]), "+f"(c[2]), "+f"(c[3])
        : "r"(a0), "r"(a1), "r"(a2), "r"(a3), "r"(b0), "r"(b1));
}

__device__ __forceinline__ void ldsm4(uint32_t& r0, uint32_t& r1,
                                      uint32_t& r2, uint32_t& r3, uint32_t addr) {
    asm volatile("ldmatrix.sync.aligned.m8n8.x4.shared.b16 {%0,%1,%2,%3}, [%4];"
                 : "=r"(r0), "=r"(r1), "=r"(r2), "=r"(r3) : "r"(addr));
}

__device__ __forceinline__ uint32_t packh2(float lo, float hi) {
    __half2 h = __floats2half2_rn(lo, hi);
    return *(uint32_t*)&h;
}

__device__ __forceinline__ void cp16(uint32_t dst, const void* src) {
    asm volatile("cp.async.ca.shared.global [%0], [%1], 16;\n" :: "r"(dst), "l"(src));
}
#define CP_COMMIT() asm volatile("cp.async.commit_group;\n" ::: "memory")
#define CP_WAIT(n)  asm volatile("cp.async.wait_group %0;\n" :: "n"(n) : "memory")

// ---------------------------------------------------------------------------
__global__ __launch_bounds__(256) void f2h(const float* __restrict__ src,
                                           __half* __restrict__ dst, int n4) {
    int i = blockIdx.x * blockDim.x + threadIdx.x;
    if (i < n4) {
        float4 v = ((const float4*)src)[i];
        ((uint2*)dst)[i] = make_uint2(packh2(v.x, v.y), packh2(v.z, v.w));
    }
}

// ---------------------------------------------------------------------------
// Weight transpose + fp16: w [1024][1024] fp32 -> wt fp16 (w^T). z: which.
// ---------------------------------------------------------------------------
__global__ __launch_bounds__(256) void wtrans(const float* __restrict__ w0,
                                              const float* __restrict__ w1,
                                              const float* __restrict__ w2,
                                              const float* __restrict__ w3,
                                              __half* __restrict__ o0,
                                              __half* __restrict__ o1,
                                              __half* __restrict__ o2,
                                              __half* __restrict__ o3) {
    const float* w = (blockIdx.z == 0) ? w0 : (blockIdx.z == 1) ? w1
                     : (blockIdx.z == 2) ? w2 : w3;
    __half* o = (blockIdx.z == 0) ? o0 : (blockIdx.z == 1) ? o1
                : (blockIdx.z == 2) ? o2 : o3;
    __shared__ __half tile[32][33];
    const int tx = threadIdx.x, ty = threadIdx.y;
    const int k0 = blockIdx.x * 32, n0 = blockIdx.y * 32;
#pragma unroll
    for (int i = 0; i < 4; i++)
        tile[ty + i * 8][tx] = __float2half_rn(w[(size_t)(k0 + ty + i * 8) * 1024 + n0 + tx]);
    __syncthreads();
#pragma unroll
    for (int i = 0; i < 4; i++)
        o[(size_t)(n0 + ty + i * 8) * 1024 + k0 + tx] = tile[tx][ty + i * 8];
}

// ---------------------------------------------------------------------------
// Fused QKV GEMM v3: 128x128 CTA tile, BK=32, 4 warps (64x64 warp tiles).
// Single-sync mainloop: CP_WAIT -> sync -> prefetch(next) -> compute.
// ---------------------------------------------------------------------------
#define HGSTR 20
#define GW (128*HGSTR)   // 2560 words per buffer

__global__ __launch_bounds__(128, 2) void gemm_qkv(const __half* __restrict__ A,
                                                   const __half* __restrict__ B0,
                                                   const __half* __restrict__ B1,
                                                   const __half* __restrict__ B2,
                                                   __half* __restrict__ qh,
                                                   __half* __restrict__ kh,
                                                   __half* __restrict__ vt) {
    const int z = blockIdx.z;
    const __half* Bt = (z == 0) ? B0 : (z == 1) ? B1 : B2;

    __shared__ uint32_t smx[4 * GW];            // As[2] | Bs[2]; aliased by tile
    uint32_t* sAb = smx;
    uint32_t* sBb = smx + 2 * GW;
    __half*   tile = (__half*)smx;              // epilogue: [128][136] halfs

    const int tid  = threadIdx.x;
    const int lane = tid & 31;
    const int warp = tid >> 5;
    const int gid  = lane >> 2;
    const int tig  = lane & 3;
    const int lm   = lane >> 3;
    const int lr   = lane & 7;
    const int wm   = (warp >> 1) * 64;
    const int wn   = (warp & 1) * 64;
    const int rowBase = blockIdx.y * 128;
    const int colBase = blockIdx.x * 128;
    const int K = Mm;

    const __half* Ag = A + (size_t)rowBase * K;
    const __half* Bg = Bt + (size_t)colBase * K;
    const uint32_t sA = (uint32_t)__cvta_generic_to_shared(sAb);
    const uint32_t sB = (uint32_t)__cvta_generic_to_shared(sBb);

    float acc[4][8][4];
#pragma unroll
    for (int mt = 0; mt < 4; mt++)
#pragma unroll
        for (int nt = 0; nt < 8; nt++)
#pragma unroll
            for (int i = 0; i < 4; i++) acc[mt][nt][i] = 0.f;

    {
#pragma unroll
        for (int i = 0; i < 4; i++) {
            const int s = tid + i * 128;
            const int r = s >> 2, c = s & 3;
            cp16(sA + (r * HGSTR + c * 4) * 4, Ag + (size_t)r * K + c * 8);
            cp16(sB + (r * HGSTR + c * 4) * 4, Bg + (size_t)r * K + c * 8);
        }
        CP_COMMIT();
    }

    const int niter = K >> 5;
    for (int it = 0; it < niter; it++) {
        const int cur = it & 1;
        CP_WAIT(0);
        __syncthreads();

        // prefetch next tile into the other buffer (proven free by the sync)
        if (it + 1 < niter) {
            const int k0 = (it + 1) << 5;
            const int nxt = (it + 1) & 1;
#pragma unroll
            for (int i = 0; i < 4; i++) {
                const int s = tid + i * 128;
                const int r = s >> 2, c = s & 3;
                cp16(sA + (nxt * GW + r * HGSTR + c * 4) * 4,
                     Ag + (size_t)r * K + k0 + c * 8);
                cp16(sB + (nxt * GW + r * HGSTR + c * 4) * 4,
                     Bg + (size_t)r * K + k0 + c * 8);
            }
            CP_COMMIT();
        }

        const uint32_t sAc = sA + cur * GW * 4;
        const uint32_t sBc = sB + cur * GW * 4;
#pragma unroll
        for (int kh2 = 0; kh2 < 2; kh2++) {
            const int kk = kh2 * 8;
            uint32_t af[4][4];
#pragma unroll
            for (int mt = 0; mt < 4; mt++) {
                const int row = wm + mt * 16 + (lm & 1) * 8 + lr;
                const int word = kk + (lm >> 1) * 4;
                ldsm4(af[mt][0], af[mt][1], af[mt][2], af[mt][3],
                      sAc + (row * HGSTR + word) * 4);
            }
#pragma unroll
            for (int np = 0; np < 4; np++) {
                const int row = wn + (2 * np + (lm >> 1)) * 8 + lr;
                const int word = kk + (lm & 1) * 4;
                uint32_t b00, b01, b10, b11;
                ldsm4(b00, b01, b10, b11, sBc + (row * HGSTR + word) * 4);
#pragma unroll
                for (int mt = 0; mt < 4; mt++) {
                    mma_f16(acc[mt][2 * np],     af[mt][0], af[mt][1], af[mt][2], af[mt][3], b00, b01);
                    mma_f16(acc[mt][2 * np + 1], af[mt][0], af[mt][1], af[mt][2], af[mt][3], b10, b11);
                }
            }
        }
        // no trailing sync: next iteration's CP_WAIT+sync provides ordering
    }
    __syncthreads();   // all warps done with As/Bs before epilogue aliases them

    // ---- epilogue ----
    const int bIdx  = rowBase >> 11;
    const int tbase = rowBase & (Tt - 1);
    const int hIdx  = colBase >> 7;

    if (z == 2) {
        // V: direct transposed scatter to [b,h,d,t]
        __half* dst = vt + ((size_t)(bIdx * Hh + hIdx) * Dd) * Tt;
#pragma unroll
        for (int mt = 0; mt < 4; mt++) {
#pragma unroll
            for (int nt = 0; nt < 8; nt++) {
                const int r0 = wm + mt * 16 + gid;
                const int c0 = wn + nt * 8 + 2 * tig;
                const int tg = tbase + r0;
                dst[(size_t)c0 * Tt + tg]           = __float2half_rn(acc[mt][nt][0]);
                dst[(size_t)(c0 + 1) * Tt + tg]     = __float2half_rn(acc[mt][nt][1]);
                dst[(size_t)c0 * Tt + tg + 8]       = __float2half_rn(acc[mt][nt][2]);
                dst[(size_t)(c0 + 1) * Tt + tg + 8] = __float2half_rn(acc[mt][nt][3]);
            }
        }
        return;
    }

    // Q/K: stage fp16 tile in smem (stride 136 halfs = 68 words)
#pragma unroll
    for (int mt = 0; mt < 4; mt++) {
#pragma unroll
        for (int nt = 0; nt < 8; nt++) {
            const int r0 = wm + mt * 16 + gid;
            const int cw = ((wn + nt * 8) >> 1) + tig;
            ((uint32_t*)tile)[r0 * 68 + cw]       = packh2(acc[mt][nt][0], acc[mt][nt][1]);
            ((uint32_t*)tile)[(r0 + 8) * 68 + cw] = packh2(acc[mt][nt][2], acc[mt][nt][3]);
        }
    }
    __syncthreads();

    // 1 thread per row; full-row RMSNorm, inline RoPE
    const int row = tid;
    const __half* trow = tile + row * 136;

    float ssq = 0.f;
#pragma unroll
    for (int j = 0; j < 64; j += 8) {
        uint4 eu = *(const uint4*)(trow + j);
        uint4 ou = *(const uint4*)(trow + 64 + j);
        const uint32_t* ew = (const uint32_t*)&eu;
        const uint32_t* ow = (const uint32_t*)&ou;
#pragma unroll
        for (int w2 = 0; w2 < 4; w2++) {
            float2 e2 = __half22float2(*(const __half2*)&ew[w2]);
            float2 o2 = __half22float2(*(const __half2*)&ow[w2]);
            ssq += e2.x * e2.x + e2.y * e2.y + o2.x * o2.x + o2.y * o2.y;
        }
    }

    const float scale = rsqrtf(ssq * (1.0f / 128.0f) + 1e-6f) * 0.08838834764831845f;
    const int tg = tbase + row;
    const float c64 = -0.20762050593017578f;   // -log2(10000)/64
    __half* dst = ((z == 0) ? qh : kh) + ((size_t)(bIdx * Hh + hIdx) * Tt + tg) * Dd;

#pragma unroll
    for (int j = 0; j < 64; j += 8) {
        uint4 eu = *(const uint4*)(trow + j);
        uint4 ou = *(const uint4*)(trow + 64 + j);
        const uint32_t* ew = (const uint32_t*)&eu;
        const uint32_t* ow = (const uint32_t*)&ou;
        uint32_t outE[4], outO[4];
#pragma unroll
        for (int w2 = 0; w2 < 4; w2++) {
            float2 e2 = __half22float2(*(const __half2*)&ew[w2]);
            float2 o2 = __half22float2(*(const __half2*)&ou);
            // note: o2 must come from ow[w2]
            o2 = __half22float2(*(const __half2*)&ow[w2]);
            float re[2], ro[2];
#pragma unroll
            for (int u = 0; u < 2; u++) {
                const int i = j + w2 * 2 + u;
                float f = exp2f((float)i * c64);
                float sn, cs;
                __sincosf((float)tg * f, &sn, &cs);
                float ev = (u ? e2.y : e2.x) * scale;
                float ov = (u ? o2.y : o2.x) * scale;
                re[u] = ev * cs - ov * sn;
                ro[u] = ev * sn + ov * cs;
            }
            outE[w2] = packh2(re[0], re[1]);
            outO[w2] = packh2(ro[0], ro[1]);
        }
        *(uint4*)(dst + j)      = *(uint4*)outE;
        *(uint4*)(dst + 64 + j) = *(uint4*)outO;
    }
}

// ---------------------------------------------------------------------------
// FP16 GEMM v3 for out-projection (single-sync mainloop).
// ---------------------------------------------------------------------------
__global__ __launch_bounds__(128, 2) void gemm_h(const __half* __restrict__ A,
                                                 const __half* __restrict__ Bt,
                                                 float* __restrict__ C,
                                                 int M, int N, int K) {
    __shared__ uint32_t As[2][GW];
    __shared__ uint32_t Bs[2][GW];

    const int tid  = threadIdx.x;
    const int lane = tid & 31;
    const int warp = tid >> 5;
    const int gid  = lane >> 2;
    const int tig  = lane & 3;
    const int lm   = lane >> 3;
    const int lr   = lane & 7;
    const int wm   = (warp >> 1) * 64;
    const int wn   = (warp & 1) * 64;
    const int rowBase = blockIdx.y * 128;
    const int colBase = blockIdx.x * 128;

    const __half* Ag = A + (size_t)rowBase * K;
    const __half* Bg = Bt + (size_t)colBase * K;
    const uint32_t sA = (uint32_t)__cvta_generic_to_shared(&As[0][0]);
    const uint32_t sB = (uint32_t)__cvta_generic_to_shared(&Bs[0][0]);

    float acc[4][8][4];
#pragma unroll
    for (int mt = 0; mt < 4; mt++)
#pragma unroll
        for (int nt = 0; nt < 8; nt++)
#pragma unroll
            for (int i = 0; i < 4; i++) acc[mt][nt][i] = 0.f;

    {
#pragma unroll
        for (int i = 0; i < 4; i++) {
            const int s = tid + i * 128;
            const int r = s >> 2, c = s & 3;
            cp16(sA + (r * HGSTR + c * 4) * 4, Ag + (size_t)r * K + c * 8);
            cp16(sB + (r * HGSTR + c * 4) * 4, Bg + (size_t)r * K + c * 8);
        }
        CP_COMMIT();
    }

    const int niter = K >> 5;
    for (int it = 0; it < niter; it++) {
        const int cur = it & 1;
        CP_WAIT(0);
        __syncthreads();

        if (it + 1 < niter) {
            const int k0 = (it + 1) << 5;
            const int nxt = (it + 1) & 1;
#pragma unroll
            for (int i = 0; i < 4; i++) {
                const int s = tid + i * 128;
                const int r = s >> 2, c = s & 3;
                cp16(sA + (nxt * GW + r * HGSTR + c * 4) * 4,
                     Ag + (size_t)r * K + k0 + c * 8);
                cp16(sB + (nxt * GW + r * HGSTR + c * 4) * 4,
                     Bg + (size_t)r * K + k0 + c * 8);
            }
            CP_COMMIT();
        }

        const uint32_t sAc = sA + cur * GW * 4;
        const uint32_t sBc = sB + cur * GW * 4;
#pragma unroll
        for (int kh2 = 0; kh2 < 2; kh2++) {
            const int kk = kh2 * 8;
            uint32_t af[4][4];
#pragma unroll
            for (int mt = 0; mt < 4; mt++) {
                const int row = wm + mt * 16 + (lm & 1) * 8 + lr;
                const int word = kk + (lm >> 1) * 4;
                ldsm4(af[mt][0], af[mt][1], af[mt][2], af[mt][3],
                      sAc + (row * HGSTR + word) * 4);
            }
#pragma unroll
            for (int np = 0; np < 4; np++) {
                const int row = wn + (2 * np + (lm >> 1)) * 8 + lr;
                const int word = kk + (lm & 1) * 4;
                uint32_t b00, b01, b10, b11;
                ldsm4(b00, b01, b10, b11, sBc + (row * HGSTR + word) * 4);
#pragma unroll
                for (int mt = 0; mt < 4; mt++) {
                    mma_f16(acc[mt][2 * np],     af[mt][0], af[mt][1], af[mt][2], af[mt][3], b00, b01);
                    mma_f16(acc[mt][2 * np + 1], af[mt][0], af[mt][1], af[mt][2], af[mt][3], b10, b11);
                }
            }
        }
    }

#pragma unroll
    for (int mt = 0; mt < 4; mt++) {
#pragma unroll
        for (int nt = 0; nt < 8; nt++) {
            const int r0 = rowBase + wm + mt * 16 + gid;
            const int c0 = colBase + wn + nt * 8 + 2 * tig;
            *(float2*)(C + (size_t)r0 * N + c0)       = make_float2(acc[mt][nt][0], acc[mt][nt][1]);
            *(float2*)(C + (size_t)(r0 + 8) * N + c0) = make_float2(acc[mt][nt][2], acc[mt][nt][3]);
        }
    }
}

// ---------------------------------------------------------------------------
// FP16 flash attention (causal), LDSM operands: BR=64 (4 warps), BC=64.
// Single-sync mainloop: CP_WAIT -> sync -> prefetch(kb+1) -> compute kb.
// ---------------------------------------------------------------------------
#define BRt 64
#define BCt 64
#define HKSTR 68
#define HVSTR 36
#define HOFF_K0 0
#define HOFF_V0 (HOFF_K0 + 64*HKSTR)
#define HOFF_K1 (HOFF_V0 + 128*HVSTR)
#define HOFF_V1 (HOFF_K1 + 64*HKSTR)
#define HSM_WORDS (HOFF_V1 + 128*HVSTR)

__global__ __launch_bounds__(128, 3) void attn_h(const __half* __restrict__ qh,
                                                 const __half* __restrict__ kh,
                                                 const __half* __restrict__ vt,
                                                 __half* __restrict__ oh) {
    extern __shared__ uint32_t smu[];

    const int tid  = threadIdx.x;
    const int lane = tid & 31;
    const int warp = tid >> 5;
    const int gid  = lane >> 2;
    const int tig  = lane & 3;
    const int lm   = lane >> 3;
    const int lr   = lane & 7;
    const int qb = (gridDim.x - 1) - blockIdx.x;
    const int h = blockIdx.y, b = blockIdx.z;
    const int t0 = qb * BRt;
    const int wrow = warp * 16;

    const size_t bhOff = (size_t)(b * Hh + h) * Tt * Dd;
    const __half* qbase = qh + bhOff + (size_t)t0 * Dd;
    const __half* kbase = kh + bhOff;
    const __half* vbase = vt + bhOff;
    const uint32_t smemBase = (uint32_t)__cvta_generic_to_shared(smu);

    const int bRowSel = lm >> 1;
    const int bKSel   = lm & 1;

    // prologue: kb=0 K/V into buf0; Q into buf1's K pane
    {
#pragma unroll
        for (int i = 0; i < 8; i++) {
            const int s = tid + i * 128;
            const int r = s >> 4, c = s & 15;
            cp16(smemBase + (HOFF_K0 + r * HKSTR + c * 4) * 4,
                 kbase + (size_t)r * Dd + c * 8);
        }
#pragma unroll
        for (int i = 0; i < 8; i++) {
            const int s = tid + i * 128;
            const int r = s >> 3, c = s & 7;
            cp16(smemBase + (HOFF_V0 + r * HVSTR + c * 4) * 4,
                 vbase + (size_t)r * Tt + c * 8);
        }
#pragma unroll
        for (int i = 0; i < 8; i++) {
            const int s = tid + i * 128;
            const int r = s >> 4, c = s & 15;
            cp16(smemBase + (HOFF_K1 + r * HKSTR + c * 4) * 4,
                 qbase + (size_t)r * Dd + c * 8);
        }
        CP_COMMIT();
        CP_WAIT(0);
    }
    __syncthreads();

    uint32_t qf[8][4];
    {
        const uint32_t qRow = wrow + (lm & 1) * 8 + lr;
        const uint32_t qWordSel = (lm >> 1) * 4;
#pragma unroll
        for (int ks = 0; ks < 8; ks++) {
            ldsm4(qf[ks][0], qf[ks][1], qf[ks][2], qf[ks][3],
                  smemBase + (HOFF_K1 + qRow * HKSTR + 8 * ks + qWordSel) * 4);
        }
    }
    __syncthreads();   // buf1 (Q pane) free for reuse as K1

    float m0 = -1e30f, m1 = -1e30f, l0 = 0.f, l1 = 0.f;
    float oacc[16][4];
#pragma unroll
    for (int nt = 0; nt < 16; nt++)
#pragma unroll
        for (int i = 0; i < 4; i++) oacc[nt][i] = 0.f;

    for (int kb = 0; kb <= qb; kb++) {
        CP_WAIT(0);        // waits group(kb), issued in previous iteration
        __syncthreads();   // also proves iteration kb-1 fully complete

        // prefetch kb+1 into the other buffer (provably free)
        if (kb + 1 <= qb) {
            const int tk0 = (kb + 1) * BCt;
            const int offK = ((kb + 1) & 1) ? HOFF_K1 : HOFF_K0;
            const int offV = ((kb + 1) & 1) ? HOFF_V1 : HOFF_V0;
#pragma unroll
            for (int i = 0; i < 8; i++) {
                const int s = tid + i * 128;
                const int r = s >> 4, c = s & 15;
                cp16(smemBase + (offK + r * HKSTR + c * 4) * 4,
                     kbase + (size_t)(tk0 + r) * Dd + c * 8);
            }
#pragma unroll
            for (int i = 0; i < 8; i++) {
                const int s = tid + i * 128;
                const int r = s >> 3, c = s & 7;
                cp16(smemBase + (offV + r * HVSTR + c * 4) * 4,
                     vbase + (size_t)r * Tt + tk0 + c * 8);
            }
            CP_COMMIT();
        }

        const uint32_t offK = (kb & 1) ? HOFF_K1 : HOFF_K0;
        const uint32_t offV = (kb & 1) ? HOFF_V1 : HOFF_V0;
        const int tk0 = kb * BCt;

        float sacc[8][4];
#pragma unroll
        for (int nt = 0; nt < 8; nt++)
#pragma unroll
            for (int i = 0; i < 4; i++) sacc[nt][i] = 0.f;

        const uint32_t kAddr0 = smemBase + (offK + ((bRowSel * 8 + lr) * HKSTR) + bKSel * 4) * 4;
#pragma unroll
        for (int ks = 0; ks < 8; ks++) {
#pragma unroll
            for (int np = 0; np < 4; np++) {
                uint32_t b00, b01, b10, b11;
                ldsm4(b00, b01, b10, b11,
                      kAddr0 + ((2 * np) * 8 * HKSTR + 8 * ks) * 4);
                mma_f16(sacc[2 * np],     qf[ks][0], qf[ks][1], qf[ks][2], qf[ks][3], b00, b01);
                mma_f16(sacc[2 * np + 1], qf[ks][0], qf[ks][1], qf[ks][2], qf[ks][3], b10, b11);
            }
        }

        if (kb == qb) {
            const int rg0 = t0 + wrow + gid;
            const int rg1 = rg0 + 8;
#pragma unroll
            for (int nt = 0; nt < 8; nt++) {
                const int cg = tk0 + nt * 8 + 2 * tig;
                if (rg0 < cg)     sacc[nt][0] = -1e30f;
                if (rg0 < cg + 1) sacc[nt][1] = -1e30f;
                if (rg1 < cg)     sacc[nt][2] = -1e30f;
                if (rg1 < cg + 1) sacc[nt][3] = -1e30f;
            }
        }

        float rm0 = -1e30f, rm1 = -1e30f;
#pragma unroll
        for (int nt = 0; nt < 8; nt++) {
            rm0 = fmaxf(rm0, fmaxf(sacc[nt][0], sacc[nt][1]));
            rm1 = fmaxf(rm1, fmaxf(sacc[nt][2], sacc[nt][3]));
        }
        rm0 = fmaxf(rm0, __shfl_xor_sync(0xffffffffu, rm0, 1));
        rm0 = fmaxf(rm0, __shfl_xor_sync(0xffffffffu, rm0, 2));
        rm1 = fmaxf(rm1, __shfl_xor_sync(0xffffffffu, rm1, 1));
        rm1 = fmaxf(rm1, __shfl_xor_sync(0xffffffffu, rm1, 2));

        const float nm0 = fmaxf(m0, rm0);
        const float nm1 = fmaxf(m1, rm1);
        float sum0 = 0.f, sum1 = 0.f;
        uint32_t pe[8][2];
#pragma unroll
        for (int nt = 0; nt < 8; nt++) {
            float e00 = __expf(sacc[nt][0] - nm0);
            float e01 = __expf(sacc[nt][1] - nm0);
            float e10 = __expf(sacc[nt][2] - nm1);
            float e11 = __expf(sacc[nt][3] - nm1);
            sum0 += e00 + e01;
            sum1 += e10 + e11;
            pe[nt][0] = packh2(e00, e01);
            pe[nt][1] = packh2(e10, e11);
        }
        sum0 += __shfl_xor_sync(0xffffffffu, sum0, 1);
        sum0 += __shfl_xor_sync(0xffffffffu, sum0, 2);
        sum1 += __shfl_xor_sync(0xffffffffu, sum1, 1);
        sum1 += __shfl_xor_sync(0xffffffffu, sum1, 2);

        const float c0 = __expf(m0 - nm0);
        const float c1 = __expf(m1 - nm1);
        l0 = l0 * c0 + sum0; m0 = nm0;
        l1 = l1 * c1 + sum1; m1 = nm1;
#pragma unroll
        for (int nt = 0; nt < 16; nt++) {
            oacc[nt][0] *= c0; oacc[nt][1] *= c0;
            oacc[nt][2] *= c1; oacc[nt][3] *= c1;
        }

        const uint32_t vAddr0 = smemBase + (offV + ((bRowSel * 8 + lr) * HVSTR) + bKSel * 4) * 4;
#pragma unroll
        for (int ks = 0; ks < 4; ks++) {
            const uint32_t a0 = pe[2 * ks][0];
            const uint32_t a1 = pe[2 * ks][1];
            const uint32_t a2 = pe[2 * ks + 1][0];
            const uint32_t a3 = pe[2 * ks + 1][1];
#pragma unroll
            for (int np = 0; np < 8; np++) {
                uint32_t b00, b01, b10, b11;
                ldsm4(b00, b01, b10, b11,
                      vAddr0 + ((2 * np) * 8 * HVSTR + 8 * ks) * 4);
                mma_f16(oacc[2 * np],     a0, a1, a2, a3, b00, b01);
                mma_f16(oacc[2 * np + 1], a0, a1, a2, a3, b10, b11);
            }
        }
        // no trailing sync
    }

    const float i0 = 1.0f / l0;
    const float i1 = 1.0f / l1;
    const int rg0 = t0 + wrow + gid;
    __half* ob0 = oh + ((size_t)(b * Tt + rg0) * Hh + h) * Dd;
    __half* ob1 = oh + ((size_t)(b * Tt + rg0 + 8) * Hh + h) * Dd;
#pragma unroll
    for (int nt = 0; nt < 16; nt++) {
        const int col = nt * 8 + 2 * tig;
        *(uint32_t*)(ob0 + col) = packh2(oacc[nt][0] * i0, oacc[nt][1] * i0);
        *(uint32_t*)(ob1 + col) = packh2(oacc[nt][2] * i1, oacc[nt][3] * i1);
    }
}

// ---------------------------------------------------------------------------
extern "C" void kernel_launch(void* const* d_in, const int* in_sizes, int n_in,
                              void* d_out, int out_size) {
    const float* x  = (const float*)d_in[0];
    const float* wq = (const float*)d_in[1];
    const float* wk = (const float*)d_in[2];
    const float* wv = (const float*)d_in[3];
    const float* wo = (const float*)d_in[4];
    float* out = (float*)d_out;

    __half *xh, *wqt, *wkt, *wvt, *wot, *qhp, *khp, *vtp, *ohp;
    cudaGetSymbolAddress((void**)&xh, g_xh);
    cudaGetSymbolAddress((void**)&wqt, g_wqt);
    cudaGetSymbolAddress((void**)&wkt, g_wkt);
    cudaGetSymbolAddress((void**)&wvt, g_wvt);
    cudaGetSymbolAddress((void**)&wot, g_wot);
    cudaGetSymbolAddress((void**)&qhp, g_qh);
    cudaGetSymbolAddress((void**)&khp, g_kh);
    cudaGetSymbolAddress((void**)&vtp, g_vt);
    cudaGetSymbolAddress((void**)&ohp, g_oh);

    // Convert x; transpose+convert all four weights
    f2h<<<(BT*Mm/4 + 255)/256, 256>>>(x, xh, BT*Mm/4);
    wtrans<<<dim3(32, 32, 4), dim3(32, 8)>>>(wq, wk, wv, wo, wqt, wkt, wvt, wot);

    // Fused QKV projections + RMSNorm/RoPE (q,k) + transpose (v)
    dim3 gp(HD / 128, BT / 128, 3);
    gemm_qkv<<<gp, 128>>>(xh, wqt, wkt, wvt, qhp, khp, vtp);

    // FP16 flash attention -> fp16 O [b,t,h,d]
    size_t smem = (size_t)HSM_WORDS * 4;
    cudaFuncSetAttribute(attn_h, cudaFuncAttributeMaxDynamicSharedMemorySize, (int)smem);
    dim3 ga(Tt / BRt, Hh, Bq);
    attn_h<<<ga, 128, smem>>>(qhp, khp, vtp, ohp);

    // Output projection -> fp32 out
    dim3 go(Mm / 128, BT / 128);
    gemm_h<<<go, 128>>>(ohp, wot, out, BT, Mm, HD);
}